// round 1
// baseline (speedup 1.0000x reference)
#include <cuda_runtime.h>

#define BATCH 8192
#define CHAN  4096
#define KWIN  5

// out[b,i] = sum_k W[i,k] * x[b, i+k-2] (zero-padded) + bias[i]
// One thread -> 4 consecutive channels via float4. Halo via scalar loads
// (L1 hits from neighbor threads). W/bias are L1-resident (80KB/16KB).
__global__ __launch_bounds__(256) void grouped_linear_kernel(
    const float* __restrict__ x,
    const float* __restrict__ W,
    const float* __restrict__ bias,
    float* __restrict__ out)
{
    const int row = blockIdx.y;
    const int c   = (blockIdx.x * blockDim.x + threadIdx.x) * 4;  // first of 4 channels
    if (c >= CHAN) return;

    const float* xr = x + (size_t)row * CHAN;

    // Center vector load (16B aligned: c is a multiple of 4)
    const float4 v = *reinterpret_cast<const float4*>(xr + c);

    // Halo (c is a multiple of 4, so c>=1 <=> c>=4; branches uniform per warp edge)
    const float xm2 = (c >= 2)       ? __ldg(xr + c - 2) : 0.0f;
    const float xm1 = (c >= 1)       ? __ldg(xr + c - 1) : 0.0f;
    const float xp4 = (c + 4 < CHAN) ? __ldg(xr + c + 4) : 0.0f;
    const float xp5 = (c + 5 < CHAN) ? __ldg(xr + c + 5) : 0.0f;

    // W rows for channels c..c+3 (20 consecutive floats, L1-cached)
    const float* w0 = W + (size_t)c * KWIN;

    float4 r;
    // out[c+0]: window xm2, xm1, v.x, v.y, v.z
    r.x = fmaf(w0[0],  xm2, fmaf(w0[1],  xm1, fmaf(w0[2],  v.x,
          fmaf(w0[3],  v.y, fmaf(w0[4],  v.z, __ldg(bias + c + 0))))));
    // out[c+1]: window xm1, v.x, v.y, v.z, v.w
    r.y = fmaf(w0[5],  xm1, fmaf(w0[6],  v.x, fmaf(w0[7],  v.y,
          fmaf(w0[8],  v.z, fmaf(w0[9],  v.w, __ldg(bias + c + 1))))));
    // out[c+2]: window v.x, v.y, v.z, v.w, xp4
    r.z = fmaf(w0[10], v.x, fmaf(w0[11], v.y, fmaf(w0[12], v.z,
          fmaf(w0[13], v.w, fmaf(w0[14], xp4, __ldg(bias + c + 2))))));
    // out[c+3]: window v.y, v.z, v.w, xp4, xp5
    r.w = fmaf(w0[15], v.y, fmaf(w0[16], v.z, fmaf(w0[17], v.w,
          fmaf(w0[18], xp4, fmaf(w0[19], xp5, __ldg(bias + c + 3))))));

    *reinterpret_cast<float4*>(out + (size_t)row * CHAN + c) = r;
}

extern "C" void kernel_launch(void* const* d_in, const int* in_sizes, int n_in,
                              void* d_out, int out_size)
{
    const float* x    = (const float*)d_in[0];
    const float* W    = (const float*)d_in[1];
    const float* bias = (const float*)d_in[2];
    float* out        = (float*)d_out;

    dim3 block(256);
    dim3 grid(CHAN / (4 * 256), BATCH);  // (4, 8192)
    grouped_linear_kernel<<<grid, block>>>(x, W, bias, out);
}

// round 2
// speedup vs baseline: 2.4815x; 2.4815x over previous
#include <cuda_runtime.h>

#define BATCH 8192
#define CHAN  4096
#define KWIN  5
#define ROWS  8      // rows per thread: amortizes W/bias register load 8x

// out[b,i] = sum_k W[i,k] * x[b, i+k-2] (zero-padded) + bias[i]
// Thread = 4 channels x 8 rows. W (20 floats) + bias (4 floats) live in
// registers for all 8 rows. Halo via two predicated float4 loads (L1-deduped
// with neighbor threads' center loads) -> all memory ops are 128-bit.
__global__ __launch_bounds__(256) void grouped_linear_kernel(
    const float* __restrict__ x,
    const float* __restrict__ W,
    const float* __restrict__ bias,
    float* __restrict__ out)
{
    const int c  = (blockIdx.x * blockDim.x + threadIdx.x) * 4;  // channel base
    const int r0 = blockIdx.y * ROWS;                            // row base

    // ---- per-thread constants: W[c..c+3][0..4] = 20 consecutive floats ----
    // byte addr = 80*t -> 16B aligned, so 5 clean LDG.128
    const float4* wv = reinterpret_cast<const float4*>(W + (size_t)c * KWIN);
    const float4 wa = wv[0];   // w0..w3
    const float4 wb = wv[1];   // w4..w7
    const float4 wc = wv[2];   // w8..w11
    const float4 wd = wv[3];   // w12..w15
    const float4 we = wv[4];   // w16..w19
    const float4 bb = *reinterpret_cast<const float4*>(bias + c);

    const bool has_left  = (c >= 4);          // c-4 load valid (c==0 is the only edge)
    const bool has_right = (c + 4 < CHAN);    // c+4 load valid
    const float4 zero4 = make_float4(0.f, 0.f, 0.f, 0.f);

    const float* xr = x   + (size_t)r0 * CHAN + c;
    float*       orp = out + (size_t)r0 * CHAN + c;

#pragma unroll
    for (int r = 0; r < ROWS; r++) {
        const float4 vl = has_left  ? *reinterpret_cast<const float4*>(xr - 4) : zero4;
        const float4 v  =             *reinterpret_cast<const float4*>(xr);
        const float4 vr = has_right ? *reinterpret_cast<const float4*>(xr + 4) : zero4;

        const float xm2 = vl.z, xm1 = vl.w, xp4 = vr.x, xp5 = vr.y;

        float4 o;
        // out[c+0]: w0*xm2 + w1*xm1 + w2*v.x + w3*v.y + w4*v.z + b
        o.x = fmaf(wa.x, xm2, fmaf(wa.y, xm1, fmaf(wa.z, v.x,
              fmaf(wa.w, v.y, fmaf(wb.x, v.z, bb.x)))));
        // out[c+1]: w5*xm1 + w6*v.x + w7*v.y + w8*v.z + w9*v.w + b
        o.y = fmaf(wb.y, xm1, fmaf(wb.z, v.x, fmaf(wb.w, v.y,
              fmaf(wc.x, v.z, fmaf(wc.y, v.w, bb.y)))));
        // out[c+2]: w10*v.x + w11*v.y + w12*v.z + w13*v.w + w14*xp4 + b
        o.z = fmaf(wc.z, v.x, fmaf(wc.w, v.y, fmaf(wd.x, v.z,
              fmaf(wd.y, v.w, fmaf(wd.z, xp4, bb.z)))));
        // out[c+3]: w15*v.y + w16*v.z + w17*v.w + w18*xp4 + w19*xp5 + b
        o.w = fmaf(wd.w, v.y, fmaf(we.x, v.z, fmaf(we.y, v.w,
              fmaf(we.z, xp4, fmaf(we.w, xp5, bb.w)))));

        *reinterpret_cast<float4*>(orp) = o;

        xr  += CHAN;
        orp += CHAN;
    }
}

extern "C" void kernel_launch(void* const* d_in, const int* in_sizes, int n_in,
                              void* d_out, int out_size)
{
    const float* x    = (const float*)d_in[0];
    const float* W    = (const float*)d_in[1];
    const float* bias = (const float*)d_in[2];
    float* out        = (float*)d_out;

    dim3 block(256);
    dim3 grid(CHAN / (4 * 256), BATCH / ROWS);  // (4, 1024)
    grouped_linear_kernel<<<grid, block>>>(x, W, bias, out);
}

// round 3
// speedup vs baseline: 2.6184x; 1.0552x over previous
#include <cuda_runtime.h>

#define BATCH 8192
#define CHAN  4096
#define KWIN  5
#define RB    4      // rows per load batch (12 independent LDG.128 in flight)
#define NB    2      // batches per thread -> 8 rows total

// out[b,i] = sum_k W[i,k] * x[b, i+k-2] (zero-padded) + bias[i]
// Thread = 4 channels x 8 rows, processed as 2 batches of 4 rows.
// Each batch issues 12 independent LDG.128 before any consumption to
// maximize outstanding DRAM traffic (latency hiding), then computes and
// streams out with evict-first stores.
__global__ __launch_bounds__(256) void grouped_linear_kernel(
    const float* __restrict__ x,
    const float* __restrict__ W,
    const float* __restrict__ bias,
    float* __restrict__ out)
{
    const int c  = (blockIdx.x * blockDim.x + threadIdx.x) * 4;  // channel base
    const int r0 = blockIdx.y * (RB * NB);                       // row base

    // Per-thread constants: W[c..c+3][0..4] = 20 floats (16B-aligned) + bias
    const float4* wv = reinterpret_cast<const float4*>(W + (size_t)c * KWIN);
    const float4 wa = wv[0];
    const float4 wb = wv[1];
    const float4 wc = wv[2];
    const float4 wd = wv[3];
    const float4 we = wv[4];
    const float4 bb = *reinterpret_cast<const float4*>(bias + c);

    const bool has_left  = (c >= 4);
    const bool has_right = (c + 4 < CHAN);
    const float4 zero4 = make_float4(0.f, 0.f, 0.f, 0.f);

    const float* xr = x   + (size_t)r0 * CHAN + c;
    float*       op = out + (size_t)r0 * CHAN + c;

#pragma unroll
    for (int h = 0; h < NB; h++) {
        float4 vl[RB], v[RB], vr[RB];

        // ---- load phase: 3*RB independent 128-bit loads ----
#pragma unroll
        for (int r = 0; r < RB; r++) {
            const float* p = xr + (size_t)r * CHAN;
            vl[r] = has_left  ? *reinterpret_cast<const float4*>(p - 4) : zero4;
            v[r]  =             *reinterpret_cast<const float4*>(p);
            vr[r] = has_right ? *reinterpret_cast<const float4*>(p + 4) : zero4;
        }

        // ---- compute + store phase ----
#pragma unroll
        for (int r = 0; r < RB; r++) {
            const float xm2 = vl[r].z, xm1 = vl[r].w;
            const float xp4 = vr[r].x, xp5 = vr[r].y;
            const float4 cv = v[r];

            float4 o;
            o.x = fmaf(wa.x, xm2,  fmaf(wa.y, xm1,  fmaf(wa.z, cv.x,
                  fmaf(wa.w, cv.y, fmaf(wb.x, cv.z, bb.x)))));
            o.y = fmaf(wb.y, xm1,  fmaf(wb.z, cv.x, fmaf(wb.w, cv.y,
                  fmaf(wc.x, cv.z, fmaf(wc.y, cv.w, bb.y)))));
            o.z = fmaf(wc.z, cv.x, fmaf(wc.w, cv.y, fmaf(wd.x, cv.z,
                  fmaf(wd.y, cv.w, fmaf(wd.z, xp4,  bb.z)))));
            o.w = fmaf(wd.w, cv.y, fmaf(we.x, cv.z, fmaf(we.y, cv.w,
                  fmaf(we.z, xp4,  fmaf(we.w, xp5,  bb.w)))));

            __stcs(reinterpret_cast<float4*>(op + (size_t)r * CHAN), o);
        }

        xr += (size_t)RB * CHAN;
        op += (size_t)RB * CHAN;
    }
}

extern "C" void kernel_launch(void* const* d_in, const int* in_sizes, int n_in,
                              void* d_out, int out_size)
{
    const float* x    = (const float*)d_in[0];
    const float* W    = (const float*)d_in[1];
    const float* bias = (const float*)d_in[2];
    float* out        = (float*)d_out;

    dim3 block(256);
    dim3 grid(CHAN / (4 * 256), BATCH / (RB * NB));  // (4, 1024)
    grouped_linear_kernel<<<grid, block>>>(x, W, bias, out);
}

// round 4
// speedup vs baseline: 2.6990x; 1.0308x over previous
#include <cuda_runtime.h>
#include <cstdint>

#define BATCH        8192
#define CHAN         4096
#define KWIN         5
#define CH_TILE      1024          // channels per CTA (256 threads * 4)
#define THREADS      256
#define DEPTH        8             // pipeline stages
#define ROWS_PER_CTA 32
#define STAGE_F4     258           // float4 per stage: [halo_l][256 main][halo_r]
#define STAGE_STRIDE 264           // padded stage stride in float4 (4224 B)

__device__ __forceinline__ void cp_async16(void* smem, const void* gmem) {
    unsigned s = (unsigned)__cvta_generic_to_shared(smem);
    asm volatile("cp.async.cg.shared.global [%0], [%1], 16;" :: "r"(s), "l"(gmem));
}
__device__ __forceinline__ void cp_commit() {
    asm volatile("cp.async.commit_group;");
}
template <int N>
__device__ __forceinline__ void cp_wait() {
    asm volatile("cp.async.wait_group %0;" :: "n"(N));
}

// out[b,i] = sum_k W[i,k] * x[b, i+k-2] (zero-padded) + bias[i]
__global__ __launch_bounds__(THREADS) void grouped_linear_kernel(
    const float* __restrict__ x,
    const float* __restrict__ W,
    const float* __restrict__ bias,
    float* __restrict__ out)
{
    __shared__ float4 smem[DEPTH * STAGE_STRIDE];   // 33792 B

    const int t   = threadIdx.x;
    const int c0  = blockIdx.x * CH_TILE;           // tile base channel
    const int c   = c0 + t * 4;                     // this thread's channels
    const int row0 = blockIdx.y * ROWS_PER_CTA;

    const bool not_first_tile = (blockIdx.x > 0);
    const bool not_last_tile  = (c0 + CH_TILE < CHAN);

    // ---- per-thread constants: W[c..c+3][0..4] (20 floats, 16B-aligned) ----
    const float4* wv = reinterpret_cast<const float4*>(W + (size_t)c * KWIN);
    const float4 wa = wv[0];
    const float4 wb = wv[1];
    const float4 wc = wv[2];
    const float4 wd = wv[3];
    const float4 we = wv[4];
    const float4 bb = *reinterpret_cast<const float4*>(bias + c);

    // ---- zero the halo slots once (edge tiles never overwrite them) ----
    if (t < DEPTH) {
        smem[t * STAGE_STRIDE + 0]            = make_float4(0.f, 0.f, 0.f, 0.f);
        smem[t * STAGE_STRIDE + STAGE_F4 - 1] = make_float4(0.f, 0.f, 0.f, 0.f);
    }
    __syncthreads();

    // gmem base for a row's stage: x[row, c0-4 ..] as float4 (16B aligned)
    const float4* gbase = reinterpret_cast<const float4*>(x + (size_t)row0 * CHAN + c0 - 4);
    const size_t  grow  = CHAN / 4;                 // float4 per row

    // ---- issue one stage: 258 float4 (thread t -> j=t+1; t0/t1 do halos) ----
    auto load_stage = [&](int stage, int r) {
        float4* sp = smem + stage * STAGE_STRIDE;
        const float4* gp = gbase + (size_t)r * grow;
        cp_async16(sp + t + 1, gp + t + 1);                       // main, always valid
        if (t == 0 && not_first_tile) cp_async16(sp, gp);          // left halo
        if (t == 1 && not_last_tile)  cp_async16(sp + 257, gp + 257); // right halo
    };

    // ---- prologue: fill DEPTH-1 stages ----
#pragma unroll
    for (int s = 0; s < DEPTH - 1; s++) {
        load_stage(s, s);
        cp_commit();
    }

    float* op = out + (size_t)row0 * CHAN + c;

    for (int i = 0; i < ROWS_PER_CTA; i++) {
        cp_wait<DEPTH - 2>();          // row i's stage complete (this thread)
        __syncthreads();               // ... and everyone else's

        // refill: row i+DEPTH-1 into stage whose readers finished at iter i-1
        const int nr = i + DEPTH - 1;
        if (nr < ROWS_PER_CTA) load_stage(nr % DEPTH, nr);
        cp_commit();                   // unconditional: keeps group counts aligned

        // ---- compute from stage i%DEPTH ----
        const float4* sp = smem + (i % DEPTH) * STAGE_STRIDE;
        const float4 s0 = sp[t];       // x[c-4..c-1]
        const float4 s1 = sp[t + 1];   // x[c  ..c+3]
        const float4 s2 = sp[t + 2];   // x[c+4..c+7]

        const float xm2 = s0.z, xm1 = s0.w;
        const float xp4 = s2.x, xp5 = s2.y;

        float4 o;
        o.x = fmaf(wa.x, xm2,  fmaf(wa.y, xm1,  fmaf(wa.z, s1.x,
              fmaf(wa.w, s1.y, fmaf(wb.x, s1.z, bb.x)))));
        o.y = fmaf(wb.y, xm1,  fmaf(wb.z, s1.x, fmaf(wb.w, s1.y,
              fmaf(wc.x, s1.z, fmaf(wc.y, s1.w, bb.y)))));
        o.z = fmaf(wc.z, s1.x, fmaf(wc.w, s1.y, fmaf(wd.x, s1.z,
              fmaf(wd.y, s1.w, fmaf(wd.z, xp4,  bb.z)))));
        o.w = fmaf(wd.w, s1.y, fmaf(we.x, s1.z, fmaf(we.y, s1.w,
              fmaf(we.z, xp4,  fmaf(we.w, xp5,  bb.w)))));

        __stcs(reinterpret_cast<float4*>(op), o);
        op += CHAN;
    }
}

extern "C" void kernel_launch(void* const* d_in, const int* in_sizes, int n_in,
                              void* d_out, int out_size)
{
    const float* x    = (const float*)d_in[0];
    const float* W    = (const float*)d_in[1];
    const float* bias = (const float*)d_in[2];
    float* out        = (float*)d_out;

    dim3 block(THREADS);
    dim3 grid(CHAN / CH_TILE, BATCH / ROWS_PER_CTA);  // (4, 256)
    grouped_linear_kernel<<<grid, block>>>(x, W, bias, out);
}